// round 15
// baseline (speedup 1.0000x reference)
#include <cuda_runtime.h>
#include <cuda_fp16.h>

typedef unsigned long long u64;
typedef unsigned int u32;

#define NMAX 100000
#define NPAD (NMAX + 128)
#define EMAX 1600000
#define NG   64
#define GTM  128   // rows per GEMM CTA

// ---- device scratch ----
__device__ __half g_ga[NPAD * 64];    // g buffers (double-buffered), fp16
__device__ __half g_gb[NPAD * 64];
__device__ __half g_hbf[NPAD * 64];   // activations fp16 (pad rows stay zero)
__device__ float  g_psum[NG * 64];
__device__ float  g_dinv[NMAX];
__device__ int    g_cnt[NMAX];        // self-resetting each replay
__device__ int    g_rank[EMAX];
__device__ int    g_rowptr[NMAX + 1];
__device__ int    g_col[EMAX];
__device__ int    g_bsums[1024];
__device__ int    g_gstart[NG];
__device__ int    g_gend[NG];
__device__ int    g_done;             // aggpool completion counter (self-resetting)

// ---------------- fused setup: psum zero + x->fp16 + count/rank + bounds ----------------
__global__ void xcb_k(const float* __restrict__ x, const int* __restrict__ dst,
                      const int* __restrict__ batch, int e, int n) {
    int i = blockIdx.x * blockDim.x + threadIdx.x;
    if (i < NG * 64) g_psum[i] = 0.f;
    if (i < n * 8) {
        const float4* xp = (const float4*)x + i * 2;
        float4 a = xp[0], b = xp[1];
        __half2 h0 = __floats2half2_rn(a.x, a.y);
        __half2 h1 = __floats2half2_rn(a.z, a.w);
        __half2 h2 = __floats2half2_rn(b.x, b.y);
        __half2 h3 = __floats2half2_rn(b.z, b.w);
        ((uint4*)g_hbf)[i] = make_uint4(*(u32*)&h0, *(u32*)&h1, *(u32*)&h2, *(u32*)&h3);
    }
    if (i < e) {
        int p = atomicAdd(&g_cnt[dst[i]], 1);
        g_rank[i] = p;
    }
    if (i < n) {
        int b = batch[i];
        if (i == 0) g_gstart[b] = 0;
        else {
            int pb = batch[i - 1];
            if (pb != b) { g_gstart[b] = i; g_gend[pb] = i - 1; }
        }
        if (i == n - 1) g_gend[b] = n - 1;
    }
}

// scan1: block-local exclusive scan of cnt -> rowptr, block totals -> bsums (+dinv, cnt reset)
__global__ void scan1_k(int n) {
    int t = threadIdx.x;
    int i = blockIdx.x * 1024 + t;
    int v = 0;
    if (i < n) {
        v = g_cnt[i];
        g_dinv[i] = rsqrtf((float)v + 1.0f);
        g_cnt[i] = 0;
    }
    int x = v;
    #pragma unroll
    for (int o = 1; o < 32; o <<= 1) {
        int y = __shfl_up_sync(0xffffffffu, x, o);
        if ((t & 31) >= o) x += y;
    }
    __shared__ int wsum[32];
    if ((t & 31) == 31) wsum[t >> 5] = x;
    __syncthreads();
    if (t < 32) {
        int y = wsum[t];
        int z = y;
        #pragma unroll
        for (int o = 1; o < 32; o <<= 1) {
            int w = __shfl_up_sync(0xffffffffu, z, o);
            if (t >= o) z += w;
        }
        wsum[t] = z - y;
        if (t == 31) g_bsums[blockIdx.x] = z;
    }
    __syncthreads();
    int excl = (x - v) + wsum[t >> 5];
    if (i < n) g_rowptr[i] = excl;
}

// scan23: each block redundantly reduces bsums[0..bid) and adds to its rowptr chunk.
__global__ void scan23_k(int n, int etot) {
    int t = threadIdx.x;
    int bid = blockIdx.x;
    __shared__ int sws[32];
    __shared__ int sOff;
    int part = 0;
    for (int j = t; j < bid; j += 1024) part += g_bsums[j];
    #pragma unroll
    for (int o = 16; o; o >>= 1) part += __shfl_xor_sync(0xffffffffu, part, o);
    if ((t & 31) == 0) sws[t >> 5] = part;
    __syncthreads();
    if (t == 0) {
        int s = 0;
        #pragma unroll
        for (int j = 0; j < 32; j++) s += sws[j];
        sOff = s;
    }
    __syncthreads();
    int i = bid * 1024 + t;
    if (i < n) g_rowptr[i] += sOff;
    if (i == 0) g_rowptr[n] = etot;
}

// atomic-free fill: position = rowptr[dst] + rank
__global__ void fill_k(const int* __restrict__ src, const int* __restrict__ dst, int e) {
    int i = blockIdx.x * blockDim.x + threadIdx.x;
    if (i < e) {
        int d = dst[i];
        g_col[__ldg(&g_rowptr[d]) + g_rank[i]] = src[i];
    }
}

// ---- gather, 4 edges per LDG pair ----
// lane = 8*grp + pos; group grp handles edge e+grp, lane loads uint4 (8 features) at pos.
// Result: acc[0..3] (float2 each) = fully reduced features 8*pos .. 8*pos+7 (all lanes).
static __device__ __forceinline__ void gather_row4(const __half* __restrict__ gbuf,
                                                   int node, int grp, int pos,
                                                   float2 acc[4]) {
    int beg = g_rowptr[node];
    int end = g_rowptr[node + 1];

    if (grp == 0) {      // self term counted once
        uint4 v = ((const uint4*)(gbuf + (size_t)node * 64))[pos];
        acc[0] = __half22float2(*(__half2*)&v.x);
        acc[1] = __half22float2(*(__half2*)&v.y);
        acc[2] = __half22float2(*(__half2*)&v.z);
        acc[3] = __half22float2(*(__half2*)&v.w);
    } else {
        acc[0] = acc[1] = acc[2] = acc[3] = make_float2(0.f, 0.f);
    }

    int e = beg;
    for (; e + 16 <= end; e += 16) {
        #pragma unroll
        for (int j = 0; j < 4; j++) {
            int idx = __ldg(&g_col[e + 4 * j + grp]);
            uint4 v = ((const uint4*)(gbuf + (size_t)idx * 64))[pos];
            float2 f0 = __half22float2(*(__half2*)&v.x);
            float2 f1 = __half22float2(*(__half2*)&v.y);
            float2 f2 = __half22float2(*(__half2*)&v.z);
            float2 f3 = __half22float2(*(__half2*)&v.w);
            acc[0].x += f0.x; acc[0].y += f0.y;
            acc[1].x += f1.x; acc[1].y += f1.y;
            acc[2].x += f2.x; acc[2].y += f2.y;
            acc[3].x += f3.x; acc[3].y += f3.y;
        }
    }
    for (; e < end; e += 4) {
        int myE = e + grp;
        if (myE < end) {
            int idx = __ldg(&g_col[myE]);
            uint4 v = ((const uint4*)(gbuf + (size_t)idx * 64))[pos];
            float2 f0 = __half22float2(*(__half2*)&v.x);
            float2 f1 = __half22float2(*(__half2*)&v.y);
            float2 f2 = __half22float2(*(__half2*)&v.z);
            float2 f3 = __half22float2(*(__half2*)&v.w);
            acc[0].x += f0.x; acc[0].y += f0.y;
            acc[1].x += f1.x; acc[1].y += f1.y;
            acc[2].x += f2.x; acc[2].y += f2.y;
            acc[3].x += f3.x; acc[3].y += f3.y;
        }
    }
    // reduce across the 4 groups (lane bits 3,4)
    #pragma unroll
    for (int j = 0; j < 4; j++) {
        acc[j].x += __shfl_xor_sync(0xffffffffu, acc[j].x, 8);
        acc[j].y += __shfl_xor_sync(0xffffffffu, acc[j].y, 8);
        acc[j].x += __shfl_xor_sync(0xffffffffu, acc[j].x, 16);
        acc[j].y += __shfl_xor_sync(0xffffffffu, acc[j].y, 16);
    }
}

// ---------------- HFMA2 GEMM (R5/R13-proven, untouched) ----------------
__global__ void __launch_bounds__(128, 4) gemm_h2_k(const float* __restrict__ W,
                                                    __half* __restrict__ gout, int n) {
    __shared__ __align__(16) unsigned char sXT[16384];
    __shared__ __align__(16) __half sWh[4096];
    __shared__ float sdinv[GTM];

    int t = threadIdx.x;
    int tile0 = blockIdx.x * GTM;

    {
        const float4* W4 = (const float4*)W;
        __half2* wh2 = (__half2*)sWh;
        #pragma unroll
        for (int j = t; j < 1024; j += 128) {
            float4 v = W4[j];
            wh2[2 * j]     = __floats2half2_rn(v.x, v.y);
            wh2[2 * j + 1] = __floats2half2_rn(v.z, v.w);
        }
    }
    if (t < GTM) {
        int r = tile0 + t;
        sdinv[t] = (r < n) ? g_dinv[r] : 0.f;
    }
    {
        int r = t;
        const uint4* hp = (const uint4*)(g_hbf + (size_t)(tile0 + r) * 64);
        int rc = r >> 3, rb = (r & 7) * 2;
        #pragma unroll
        for (int q = 0; q < 8; q++) {
            uint4 v = hp[q];
            __half h[8];
            *(uint4*)h = v;
            #pragma unroll
            for (int j = 0; j < 8; j++) {
                int k = 8 * q + j;
                *(__half*)(sXT + k * 256 + ((rc ^ (k & 15)) << 4) + rb) = h[j];
            }
        }
    }
    __syncthreads();

    int rg = t & 15;
    int cgp = t >> 4;

    float fac[64];
    #pragma unroll
    for (int a = 0; a < 64; a++) fac[a] = 0.f;

    #pragma unroll
    for (int half = 0; half < 2; half++) {
        __half2 acc[32];
        #pragma unroll
        for (int a = 0; a < 32; a++) acc[a] = __floats2half2_rn(0.f, 0.f);

        #pragma unroll 8
        for (int kk = 0; kk < 32; kk++) {
            int k = half * 32 + kk;
            uint4 xv = *(const uint4*)(sXT + k * 256 + ((rg ^ (k & 15)) << 4));
            uint4 wv = *(const uint4*)(sWh + (size_t)k * 64 + cgp * 8);
            __half2 w0 = *(__half2*)&wv.x, w1 = *(__half2*)&wv.y;
            __half2 w2 = *(__half2*)&wv.z, w3 = *(__half2*)&wv.w;
            u32 xw[4] = {xv.x, xv.y, xv.z, xv.w};
            #pragma unroll
            for (int p = 0; p < 4; p++) {
                __half2 xpair = *(__half2*)&xw[p];
                __half2 xlo = __low2half2(xpair);
                __half2 xhi = __high2half2(xpair);
                acc[(2 * p) * 4 + 0] = __hfma2(xlo, w0, acc[(2 * p) * 4 + 0]);
                acc[(2 * p) * 4 + 1] = __hfma2(xlo, w1, acc[(2 * p) * 4 + 1]);
                acc[(2 * p) * 4 + 2] = __hfma2(xlo, w2, acc[(2 * p) * 4 + 2]);
                acc[(2 * p) * 4 + 3] = __hfma2(xlo, w3, acc[(2 * p) * 4 + 3]);
                acc[(2 * p + 1) * 4 + 0] = __hfma2(xhi, w0, acc[(2 * p + 1) * 4 + 0]);
                acc[(2 * p + 1) * 4 + 1] = __hfma2(xhi, w1, acc[(2 * p + 1) * 4 + 1]);
                acc[(2 * p + 1) * 4 + 2] = __hfma2(xhi, w2, acc[(2 * p + 1) * 4 + 2]);
                acc[(2 * p + 1) * 4 + 3] = __hfma2(xhi, w3, acc[(2 * p + 1) * 4 + 3]);
            }
        }
        #pragma unroll
        for (int j = 0; j < 8; j++)
            #pragma unroll
            for (int cp = 0; cp < 4; cp++) {
                float2 f = __half22float2(acc[j * 4 + cp]);
                fac[j * 8 + 2 * cp]     += f.x;
                fac[j * 8 + 2 * cp + 1] += f.y;
            }
    }

    #pragma unroll
    for (int j = 0; j < 8; j++) {
        int r = 8 * rg + j;
        int node = tile0 + r;
        if (node < n) {
            float di = sdinv[r];
            __half2 o[4];
            #pragma unroll
            for (int cp = 0; cp < 4; cp++)
                o[cp] = __floats2half2_rn(fac[j * 8 + 2 * cp] * di,
                                          fac[j * 8 + 2 * cp + 1] * di);
            ((uint4*)(gout + (size_t)node * 64))[cgp] = *(uint4*)o;
        }
    }
}

// ---------------- aggregation (one warp per node, low-LSU gather) ----------------
__global__ void __launch_bounds__(256) agg64_k(const float* __restrict__ bias,
                                               const __half* __restrict__ gin, int n) {
    int node = (blockIdx.x * blockDim.x + threadIdx.x) >> 5;
    int lane = threadIdx.x & 31;
    if (node >= n) return;
    int grp = lane >> 3, pos = lane & 7;

    float2 acc[4];
    gather_row4(gin, node, grp, pos, acc);

    float di = g_dinv[node];
    float4 bA = ((const float4*)bias)[2 * pos];
    float4 bB = ((const float4*)bias)[2 * pos + 1];
    float o0 = fmaxf(di * acc[0].x + bA.x, 0.f);
    float o1 = fmaxf(di * acc[0].y + bA.y, 0.f);
    float o2 = fmaxf(di * acc[1].x + bA.z, 0.f);
    float o3 = fmaxf(di * acc[1].y + bA.w, 0.f);
    float o4 = fmaxf(di * acc[2].x + bB.x, 0.f);
    float o5 = fmaxf(di * acc[2].y + bB.y, 0.f);
    float o6 = fmaxf(di * acc[3].x + bB.z, 0.f);
    float o7 = fmaxf(di * acc[3].y + bB.w, 0.f);
    if (grp == 0) {
        __half2 h0 = __floats2half2_rn(o0, o1);
        __half2 h1 = __floats2half2_rn(o2, o3);
        __half2 h2 = __floats2half2_rn(o4, o5);
        __half2 h3 = __floats2half2_rn(o6, o7);
        ((uint4*)(g_hbf + (size_t)node * 64))[pos] =
            make_uint4(*(u32*)&h0, *(u32*)&h1, *(u32*)&h2, *(u32*)&h3);
    }
}

// ---------------- fused agg3 + pool + final head (low-LSU gather) ----------------
__global__ void __launch_bounds__(256) aggpoolfin_k(const float* __restrict__ bias,
                                                    const int* __restrict__ batch,
                                                    const __half* __restrict__ gin,
                                                    const float* __restrict__ Wl,
                                                    const float* __restrict__ bl,
                                                    float* __restrict__ out,
                                                    int n, int nblk) {
    int t = threadIdx.x;
    int lane = t & 31;
    int w = t >> 5;
    int grp = lane >> 3, pos = lane & 7;
    int base = (blockIdx.x * 8 + w) * 8;

    float4 bA = ((const float4*)bias)[2 * pos];
    float4 bB = ((const float4*)bias)[2 * pos + 1];

    float ps[8];
    #pragma unroll
    for (int j = 0; j < 8; j++) ps[j] = 0.f;
    int curg = -1;

    #pragma unroll 1
    for (int i = 0; i < 8; i++) {
        int node = base + i;
        if (node >= n) break;
        float2 acc[4];
        gather_row4(gin, node, grp, pos, acc);
        float di = g_dinv[node];
        int bg = batch[node];
        if (bg != curg) {
            if (curg >= 0 && grp == 0) {
                #pragma unroll
                for (int j = 0; j < 8; j++)
                    atomicAdd(&g_psum[curg * 64 + 8 * pos + j], ps[j]);
            }
            #pragma unroll
            for (int j = 0; j < 8; j++) ps[j] = 0.f;
            curg = bg;
        }
        ps[0] += di * acc[0].x + bA.x;
        ps[1] += di * acc[0].y + bA.y;
        ps[2] += di * acc[1].x + bA.z;
        ps[3] += di * acc[1].y + bA.w;
        ps[4] += di * acc[2].x + bB.x;
        ps[5] += di * acc[2].y + bB.y;
        ps[6] += di * acc[3].x + bB.z;
        ps[7] += di * acc[3].y + bB.w;
    }
    if (curg >= 0 && grp == 0) {
        #pragma unroll
        for (int j = 0; j < 8; j++)
            atomicAdd(&g_psum[curg * 64 + 8 * pos + j], ps[j]);
    }

    // last-done block computes the head
    __shared__ int sLast;
    __syncthreads();
    if (t == 0) {
        __threadfence();
        sLast = (atomicAdd(&g_done, 1) == nblk - 1) ? 1 : 0;
    }
    __syncthreads();
    if (sLast) {
        __threadfence();
        if (t < 128) {
            int g = t >> 1, c = t & 1;
            float s = 0.f;
            #pragma unroll
            for (int k = 0; k < 64; k++) s += g_psum[g * 64 + k] * Wl[k * 2 + c];
            int st = g_gstart[g], en = g_gend[g];
            float cf = (en >= st) ? (float)(en - st + 1) : 0.f;
            out[t] = s / fmaxf(cf, 1.f) + bl[c];
        }
        __syncthreads();
        if (t == 0) { *(volatile int*)&g_done = 0; __threadfence(); }
    }
}

// ---------------- launch ----------------

extern "C" void kernel_launch(void* const* d_in, const int* in_sizes, int n_in,
                              void* d_out, int out_size) {
    const float* x     = (const float*)d_in[0];
    const int*   ei    = (const int*)d_in[1];
    const int*   batch = (const int*)d_in[2];
    const float* W1 = (const float*)d_in[3]; const float* b1 = (const float*)d_in[4];
    const float* W2 = (const float*)d_in[5]; const float* b2 = (const float*)d_in[6];
    const float* W3 = (const float*)d_in[7]; const float* b3 = (const float*)d_in[8];
    const float* Wl = (const float*)d_in[9]; const float* bl = (const float*)d_in[10];

    int n = in_sizes[0] / 64;
    int e = in_sizes[1] / 2;
    const int* src = ei;
    const int* dst = ei + e;

    int nb = (n + 1023) / 1024;
    int ntile = (n + GTM - 1) / GTM;
    int mthreads = (e > n * 8) ? e : n * 8;

    __half *ga, *gb;
    cudaGetSymbolAddress((void**)&ga, g_ga);
    cudaGetSymbolAddress((void**)&gb, g_gb);

    cudaStream_t sB;
    cudaStreamCreateWithFlags(&sB, cudaStreamNonBlocking);
    cudaEvent_t eD, eF;
    cudaEventCreateWithFlags(&eD, cudaEventDisableTiming);
    cudaEventCreateWithFlags(&eF, cudaEventDisableTiming);

    // setup: fused conversion + count + bounds, then scan1
    xcb_k  <<<(mthreads + 255) / 256, 256>>>(x, dst, batch, e, n);
    scan1_k<<<nb, 1024>>>(n);
    cudaEventRecord(eD, 0);                      // dinv + bsums ready

    // fork: CSR finalization on sB overlaps gemm1 on stream 0
    cudaStreamWaitEvent(sB, eD, 0);
    scan23_k<<<nb, 1024, 0, sB>>>(n, e);
    fill_k  <<<(e + 255) / 256, 256, 0, sB>>>(src, dst, e);
    cudaEventRecord(eF, sB);                     // CSR ready

    gemm_h2_k<<<ntile, 128>>>(W1, ga, n);        // needs dinv + g_hbf only

    // layers (sequential)
    cudaStreamWaitEvent(0, eF, 0);
    int apblk = (n + 63) / 64;
    agg64_k    <<<(n + 7) / 8, 256>>>(b1, ga, n);
    gemm_h2_k  <<<ntile, 128>>>(W2, gb, n);
    agg64_k    <<<(n + 7) / 8, 256>>>(b2, gb, n);
    gemm_h2_k  <<<ntile, 128>>>(W3, ga, n);
    aggpoolfin_k<<<apblk, 256>>>(b3, batch, ga, Wl, bl, (float*)d_out, n, apblk);
}

// round 16
// speedup vs baseline: 1.1206x; 1.1206x over previous
#include <cuda_runtime.h>
#include <cuda_fp16.h>

typedef unsigned long long u64;
typedef unsigned int u32;

#define NMAX 100000
#define NPAD (NMAX + 128)
#define EMAX 1600000
#define NG   64
#define GTM  128   // rows per GEMM CTA

// ---- device scratch ----
__device__ __half g_ga[NPAD * 64];    // g buffers (double-buffered), fp16
__device__ __half g_gb[NPAD * 64];
__device__ __half g_hbf[NPAD * 64];   // activations fp16 (pad rows stay zero)
__device__ float  g_psum[NG * 64];
__device__ float  g_dinv[NMAX];
__device__ int    g_cnt[NMAX];        // self-resetting each replay
__device__ int    g_rank[EMAX];
__device__ int    g_rowptr[NMAX + 1];
__device__ int    g_col[EMAX];
__device__ int    g_bsums[1024];
__device__ int    g_gstart[NG];
__device__ int    g_gend[NG];
__device__ int    g_done;             // aggpool completion counter (self-resetting)

// ---------------- fused setup: psum zero + x->fp16 + count/rank + bounds ----------------
__global__ void xcb_k(const float* __restrict__ x, const int* __restrict__ dst,
                      const int* __restrict__ batch, int e, int n) {
    int i = blockIdx.x * blockDim.x + threadIdx.x;
    if (i < NG * 64) g_psum[i] = 0.f;
    if (i < n * 8) {
        const float4* xp = (const float4*)x + i * 2;
        float4 a = xp[0], b = xp[1];
        __half2 h0 = __floats2half2_rn(a.x, a.y);
        __half2 h1 = __floats2half2_rn(a.z, a.w);
        __half2 h2 = __floats2half2_rn(b.x, b.y);
        __half2 h3 = __floats2half2_rn(b.z, b.w);
        ((uint4*)g_hbf)[i] = make_uint4(*(u32*)&h0, *(u32*)&h1, *(u32*)&h2, *(u32*)&h3);
    }
    if (i < e) {
        int p = atomicAdd(&g_cnt[dst[i]], 1);
        g_rank[i] = p;
    }
    if (i < n) {
        int b = batch[i];
        if (i == 0) g_gstart[b] = 0;
        else {
            int pb = batch[i - 1];
            if (pb != b) { g_gstart[b] = i; g_gend[pb] = i - 1; }
        }
        if (i == n - 1) g_gend[b] = n - 1;
    }
}

// scan1: block-local exclusive scan of cnt -> rowptr, block totals -> bsums (+dinv, cnt reset)
__global__ void scan1_k(int n) {
    int t = threadIdx.x;
    int i = blockIdx.x * 1024 + t;
    int v = 0;
    if (i < n) {
        v = g_cnt[i];
        g_dinv[i] = rsqrtf((float)v + 1.0f);
        g_cnt[i] = 0;
    }
    int x = v;
    #pragma unroll
    for (int o = 1; o < 32; o <<= 1) {
        int y = __shfl_up_sync(0xffffffffu, x, o);
        if ((t & 31) >= o) x += y;
    }
    __shared__ int wsum[32];
    if ((t & 31) == 31) wsum[t >> 5] = x;
    __syncthreads();
    if (t < 32) {
        int y = wsum[t];
        int z = y;
        #pragma unroll
        for (int o = 1; o < 32; o <<= 1) {
            int w = __shfl_up_sync(0xffffffffu, z, o);
            if (t >= o) z += w;
        }
        wsum[t] = z - y;
        if (t == 31) g_bsums[blockIdx.x] = z;
    }
    __syncthreads();
    int excl = (x - v) + wsum[t >> 5];
    if (i < n) g_rowptr[i] = excl;
}

// scan23: each block redundantly reduces bsums[0..bid) and adds to its rowptr chunk.
__global__ void scan23_k(int n, int etot) {
    int t = threadIdx.x;
    int bid = blockIdx.x;
    __shared__ int sws[32];
    __shared__ int sOff;
    int part = 0;
    for (int j = t; j < bid; j += 1024) part += g_bsums[j];
    #pragma unroll
    for (int o = 16; o; o >>= 1) part += __shfl_xor_sync(0xffffffffu, part, o);
    if ((t & 31) == 0) sws[t >> 5] = part;
    __syncthreads();
    if (t == 0) {
        int s = 0;
        #pragma unroll
        for (int j = 0; j < 32; j++) s += sws[j];
        sOff = s;
    }
    __syncthreads();
    int i = bid * 1024 + t;
    if (i < n) g_rowptr[i] += sOff;
    if (i == 0) g_rowptr[n] = etot;
}

// atomic-free fill: position = rowptr[dst] + rank
__global__ void fill_k(const int* __restrict__ src, const int* __restrict__ dst, int e) {
    int i = blockIdx.x * blockDim.x + threadIdx.x;
    if (i < e) {
        int d = dst[i];
        g_col[__ldg(&g_rowptr[d]) + g_rank[i]] = src[i];
    }
}

// ---- shared gather: fp32 edge-sum of g rows; row loads bypass L1 (__ldcg) ----
static __device__ __forceinline__ float2 gather_sum(const __half2* __restrict__ g2,
                                                    int node, int lane) {
    int beg = g_rowptr[node];
    int end = g_rowptr[node + 1];
    float2 acc = __half22float2(__ldcg(&g2[(size_t)node * 32 + lane]));   // self term
    int e = beg;
    for (; e + 8 <= end; e += 8) {
        int s0 = __ldg(&g_col[e + 0]);
        int s1 = __ldg(&g_col[e + 1]);
        int s2 = __ldg(&g_col[e + 2]);
        int s3 = __ldg(&g_col[e + 3]);
        int s4 = __ldg(&g_col[e + 4]);
        int s5 = __ldg(&g_col[e + 5]);
        int s6 = __ldg(&g_col[e + 6]);
        int s7 = __ldg(&g_col[e + 7]);
        __half2 v0 = __ldcg(&g2[(size_t)s0 * 32 + lane]);
        __half2 v1 = __ldcg(&g2[(size_t)s1 * 32 + lane]);
        __half2 v2 = __ldcg(&g2[(size_t)s2 * 32 + lane]);
        __half2 v3 = __ldcg(&g2[(size_t)s3 * 32 + lane]);
        __half2 v4 = __ldcg(&g2[(size_t)s4 * 32 + lane]);
        __half2 v5 = __ldcg(&g2[(size_t)s5 * 32 + lane]);
        __half2 v6 = __ldcg(&g2[(size_t)s6 * 32 + lane]);
        __half2 v7 = __ldcg(&g2[(size_t)s7 * 32 + lane]);
        float2 f0 = __half22float2(v0), f1 = __half22float2(v1);
        float2 f2 = __half22float2(v2), f3 = __half22float2(v3);
        float2 f4 = __half22float2(v4), f5 = __half22float2(v5);
        float2 f6 = __half22float2(v6), f7 = __half22float2(v7);
        acc.x += ((f0.x + f1.x) + (f2.x + f3.x)) + ((f4.x + f5.x) + (f6.x + f7.x));
        acc.y += ((f0.y + f1.y) + (f2.y + f3.y)) + ((f4.y + f5.y) + (f6.y + f7.y));
    }
    for (; e < end; e++) {
        int s = __ldg(&g_col[e]);
        float2 v = __half22float2(__ldcg(&g2[(size_t)s * 32 + lane]));
        acc.x += v.x; acc.y += v.y;
    }
    return acc;
}

// ---------------- HFMA2 GEMM (R5/R13-proven, untouched) ----------------
__global__ void __launch_bounds__(128, 4) gemm_h2_k(const float* __restrict__ W,
                                                    __half* __restrict__ gout, int n) {
    __shared__ __align__(16) unsigned char sXT[16384];
    __shared__ __align__(16) __half sWh[4096];
    __shared__ float sdinv[GTM];

    int t = threadIdx.x;
    int tile0 = blockIdx.x * GTM;

    {
        const float4* W4 = (const float4*)W;
        __half2* wh2 = (__half2*)sWh;
        #pragma unroll
        for (int j = t; j < 1024; j += 128) {
            float4 v = W4[j];
            wh2[2 * j]     = __floats2half2_rn(v.x, v.y);
            wh2[2 * j + 1] = __floats2half2_rn(v.z, v.w);
        }
    }
    if (t < GTM) {
        int r = tile0 + t;
        sdinv[t] = (r < n) ? g_dinv[r] : 0.f;
    }
    {
        int r = t;
        const uint4* hp = (const uint4*)(g_hbf + (size_t)(tile0 + r) * 64);
        int rc = r >> 3, rb = (r & 7) * 2;
        #pragma unroll
        for (int q = 0; q < 8; q++) {
            uint4 v = hp[q];
            __half h[8];
            *(uint4*)h = v;
            #pragma unroll
            for (int j = 0; j < 8; j++) {
                int k = 8 * q + j;
                *(__half*)(sXT + k * 256 + ((rc ^ (k & 15)) << 4) + rb) = h[j];
            }
        }
    }
    __syncthreads();

    int rg = t & 15;
    int cgp = t >> 4;

    float fac[64];
    #pragma unroll
    for (int a = 0; a < 64; a++) fac[a] = 0.f;

    #pragma unroll
    for (int half = 0; half < 2; half++) {
        __half2 acc[32];
        #pragma unroll
        for (int a = 0; a < 32; a++) acc[a] = __floats2half2_rn(0.f, 0.f);

        #pragma unroll 8
        for (int kk = 0; kk < 32; kk++) {
            int k = half * 32 + kk;
            uint4 xv = *(const uint4*)(sXT + k * 256 + ((rg ^ (k & 15)) << 4));
            uint4 wv = *(const uint4*)(sWh + (size_t)k * 64 + cgp * 8);
            __half2 w0 = *(__half2*)&wv.x, w1 = *(__half2*)&wv.y;
            __half2 w2 = *(__half2*)&wv.z, w3 = *(__half2*)&wv.w;
            u32 xw[4] = {xv.x, xv.y, xv.z, xv.w};
            #pragma unroll
            for (int p = 0; p < 4; p++) {
                __half2 xpair = *(__half2*)&xw[p];
                __half2 xlo = __low2half2(xpair);
                __half2 xhi = __high2half2(xpair);
                acc[(2 * p) * 4 + 0] = __hfma2(xlo, w0, acc[(2 * p) * 4 + 0]);
                acc[(2 * p) * 4 + 1] = __hfma2(xlo, w1, acc[(2 * p) * 4 + 1]);
                acc[(2 * p) * 4 + 2] = __hfma2(xlo, w2, acc[(2 * p) * 4 + 2]);
                acc[(2 * p) * 4 + 3] = __hfma2(xlo, w3, acc[(2 * p) * 4 + 3]);
                acc[(2 * p + 1) * 4 + 0] = __hfma2(xhi, w0, acc[(2 * p + 1) * 4 + 0]);
                acc[(2 * p + 1) * 4 + 1] = __hfma2(xhi, w1, acc[(2 * p + 1) * 4 + 1]);
                acc[(2 * p + 1) * 4 + 2] = __hfma2(xhi, w2, acc[(2 * p + 1) * 4 + 2]);
                acc[(2 * p + 1) * 4 + 3] = __hfma2(xhi, w3, acc[(2 * p + 1) * 4 + 3]);
            }
        }
        #pragma unroll
        for (int j = 0; j < 8; j++)
            #pragma unroll
            for (int cp = 0; cp < 4; cp++) {
                float2 f = __half22float2(acc[j * 4 + cp]);
                fac[j * 8 + 2 * cp]     += f.x;
                fac[j * 8 + 2 * cp + 1] += f.y;
            }
    }

    #pragma unroll
    for (int j = 0; j < 8; j++) {
        int r = 8 * rg + j;
        int node = tile0 + r;
        if (node < n) {
            float di = sdinv[r];
            __half2 o[4];
            #pragma unroll
            for (int cp = 0; cp < 4; cp++)
                o[cp] = __floats2half2_rn(fac[j * 8 + 2 * cp] * di,
                                          fac[j * 8 + 2 * cp + 1] * di);
            ((uint4*)(gout + (size_t)node * 64))[cgp] = *(uint4*)o;
        }
    }
}

// ---------------- aggregation (one warp per node) ----------------
__global__ void __launch_bounds__(256) agg64_k(const float* __restrict__ bias,
                                               const __half* __restrict__ gin, int n) {
    int node = (blockIdx.x * blockDim.x + threadIdx.x) >> 5;
    int lane = threadIdx.x & 31;
    if (node >= n) return;

    float2 acc = gather_sum((const __half2*)gin, node, lane);
    float di = g_dinv[node];
    float2 b = ((const float2*)bias)[lane];
    float ox = fmaxf(di * acc.x + b.x, 0.f);
    float oy = fmaxf(di * acc.y + b.y, 0.f);
    ((__half2*)g_hbf)[(size_t)node * 32 + lane] = __floats2half2_rn(ox, oy);
}

// ---------------- fused agg3 + pool + final head (done-counter) ----------------
__global__ void __launch_bounds__(256) aggpoolfin_k(const float* __restrict__ bias,
                                                    const int* __restrict__ batch,
                                                    const __half* __restrict__ gin,
                                                    const float* __restrict__ Wl,
                                                    const float* __restrict__ bl,
                                                    float* __restrict__ out,
                                                    int n, int nblk) {
    int t = threadIdx.x;
    int w = t >> 5, lane = t & 31;
    int base = (blockIdx.x * 8 + w) * 8;
    float2 b = ((const float2*)bias)[lane];
    const __half2* g2 = (const __half2*)gin;

    float2 ps = make_float2(0.f, 0.f);
    int curg = -1;
    #pragma unroll 1
    for (int i = 0; i < 8; i++) {
        int node = base + i;
        if (node >= n) break;
        float2 acc = gather_sum(g2, node, lane);
        float di = g_dinv[node];
        float ox = di * acc.x + b.x;
        float oy = di * acc.y + b.y;
        int bg = batch[node];
        if (bg != curg) {
            if (curg >= 0) {
                atomicAdd(&g_psum[curg * 64 + 2 * lane], ps.x);
                atomicAdd(&g_psum[curg * 64 + 2 * lane + 1], ps.y);
            }
            ps = make_float2(0.f, 0.f);
            curg = bg;
        }
        ps.x += ox; ps.y += oy;
    }
    if (curg >= 0) {
        atomicAdd(&g_psum[curg * 64 + 2 * lane], ps.x);
        atomicAdd(&g_psum[curg * 64 + 2 * lane + 1], ps.y);
    }

    // last-done block computes the head
    __shared__ int sLast;
    __syncthreads();
    if (t == 0) {
        __threadfence();
        sLast = (atomicAdd(&g_done, 1) == nblk - 1) ? 1 : 0;
    }
    __syncthreads();
    if (sLast) {
        __threadfence();
        if (t < 128) {
            int g = t >> 1, c = t & 1;
            float s = 0.f;
            #pragma unroll
            for (int k = 0; k < 64; k++) s += g_psum[g * 64 + k] * Wl[k * 2 + c];
            int st = g_gstart[g], en = g_gend[g];
            float cf = (en >= st) ? (float)(en - st + 1) : 0.f;
            out[t] = s / fmaxf(cf, 1.f) + bl[c];
        }
        __syncthreads();
        if (t == 0) { *(volatile int*)&g_done = 0; __threadfence(); }
    }
}

// ---------------- launch ----------------

extern "C" void kernel_launch(void* const* d_in, const int* in_sizes, int n_in,
                              void* d_out, int out_size) {
    const float* x     = (const float*)d_in[0];
    const int*   ei    = (const int*)d_in[1];
    const int*   batch = (const int*)d_in[2];
    const float* W1 = (const float*)d_in[3]; const float* b1 = (const float*)d_in[4];
    const float* W2 = (const float*)d_in[5]; const float* b2 = (const float*)d_in[6];
    const float* W3 = (const float*)d_in[7]; const float* b3 = (const float*)d_in[8];
    const float* Wl = (const float*)d_in[9]; const float* bl = (const float*)d_in[10];

    int n = in_sizes[0] / 64;
    int e = in_sizes[1] / 2;
    const int* src = ei;
    const int* dst = ei + e;

    int nb = (n + 1023) / 1024;
    int ntile = (n + GTM - 1) / GTM;
    int mthreads = (e > n * 8) ? e : n * 8;

    __half *ga, *gb;
    cudaGetSymbolAddress((void**)&ga, g_ga);
    cudaGetSymbolAddress((void**)&gb, g_gb);

    cudaStream_t sB;
    cudaStreamCreateWithFlags(&sB, cudaStreamNonBlocking);
    cudaEvent_t eD, eF;
    cudaEventCreateWithFlags(&eD, cudaEventDisableTiming);
    cudaEventCreateWithFlags(&eF, cudaEventDisableTiming);

    // setup: fused conversion + count + bounds, then scan1
    xcb_k  <<<(mthreads + 255) / 256, 256>>>(x, dst, batch, e, n);
    scan1_k<<<nb, 1024>>>(n);
    cudaEventRecord(eD, 0);                      // dinv + bsums ready

    // fork: CSR finalization on sB overlaps gemm1 on stream 0
    cudaStreamWaitEvent(sB, eD, 0);
    scan23_k<<<nb, 1024, 0, sB>>>(n, e);
    fill_k  <<<(e + 255) / 256, 256, 0, sB>>>(src, dst, e);
    cudaEventRecord(eF, sB);                     // CSR ready

    gemm_h2_k<<<ntile, 128>>>(W1, ga, n);        // needs dinv + g_hbf only

    // layers (sequential)
    cudaStreamWaitEvent(0, eF, 0);
    int apblk = (n + 63) / 64;
    agg64_k    <<<(n + 7) / 8, 256>>>(b1, ga, n);
    gemm_h2_k  <<<ntile, 128>>>(W2, gb, n);
    agg64_k    <<<(n + 7) / 8, 256>>>(b2, gb, n);
    gemm_h2_k  <<<ntile, 128>>>(W3, ga, n);
    aggpoolfin_k<<<apblk, 256>>>(b3, batch, ga, Wl, bl, (float*)d_out, n, apblk);
}